// round 12
// baseline (speedup 1.0000x reference)
#include <cuda_runtime.h>
#include <cuda_fp16.h>

#define WARP_FULL 0xFFFFFFFFu

namespace {
constexpr int NMAX = 100000;
constexpr int EMAX = 3200000;
constexpr int HD = 32;
constexpr int NLAYER = 3;
constexpr int SCAN_CHUNK = 4096;   // 1024 threads * 4 items
constexpr int MAXCHUNK = 64;
constexpr int TILE = 256;          // nodes per block-tile in thread-per-node kernels
}

// ---- persistent device scratch (module-load zero-init; no runtime allocs) ----
__device__ __align__(128) __half g_Ah[(size_t)NMAX * HD];   // fp16 message precursor rows (64 B/row)
__device__ __align__(128) float  g_h[(size_t)NMAX * HD];
__device__ __align__(16)  float  g_V[(size_t)NMAX * 2];
__device__ __align__(16)  float  g_Cfeat[(size_t)NMAX * 4];
__device__ float g_Ccnt[NMAX];
__device__ int   g_deg[NMAX];        // zero at entry (reset by k_scatter of previous call)
__device__ int   g_rowptr[NMAX + 1];
__device__ int   g_cursor[NMAX];
// one 16-byte record per edge, CSR order: {send, mask bits, half2(mask*ef01), half2(mask*ef23)}
__device__ __align__(128) uint4 g_rec[EMAX];
__device__ float g_pooled[NLAYER * HD];           // zero at entry (reset by k_scatter)
__device__ float g_gst2[NLAYER + 1][HD];          // gst2[0] zero at entry (reset by k_scatter)
__device__ int   g_scanstate[MAXCHUNK];           // zero at entry (reset by k_scatter)

// ---------------------------------------------------------------- launch 0: histogram + A0/V init (thread-per-node)
__global__ __launch_bounds__(256) void k_histinit(
    const int* __restrict__ recv, int e,
    const float2* __restrict__ PQ, const float* __restrict__ Win,
    const float* __restrict__ bin, const float* __restrict__ Wmsg0, int n) {
    __shared__ float sWin0[HD], sWin1[HD], sbin[HD], sWm[34 * HD];
    int tid = threadIdx.x;
    if (tid < HD) { sWin0[tid] = Win[tid]; sWin1[tid] = Win[HD + tid]; sbin[tid] = bin[tid]; }
    for (int i = tid; i < 34 * HD; i += 256) sWm[i] = Wmsg0[i];
    __syncthreads();

    // phase 1: receiver histogram (index clamped)
    int gid = blockIdx.x * 256 + tid, gs = gridDim.x * 256;
    for (int i = gid; i < e; i += gs) {
        int r = recv[i];
        r = min(max(r, 0), n - 1);
        atomicAdd(&g_deg[r], 1);
    }

    // phase 2: thread-per-node A0 = [1,0,h0] @ Wmsg0[:34]; V init
    for (int tb = blockIdx.x * TILE; tb < n; tb += gridDim.x * TILE) {
        int node = tb + tid;
        if (node < n) {
            float2 pq = PQ[node];
            float h0[HD];
#pragma unroll
            for (int c = 0; c < HD; c++)
                h0[c] = pq.x * sWin0[c] + pq.y * sWin1[c] + sbin[c];
            float a[HD];
#pragma unroll
            for (int c = 0; c < HD; c++) a[c] = sWm[c];   // V = (1,0): row 0
#pragma unroll
            for (int k = 0; k < HD; k++) {
                float hk = h0[k];
#pragma unroll
                for (int c = 0; c < HD; c++) a[c] += hk * sWm[(2 + k) * HD + c];
            }
            size_t base = (size_t)node * HD;
#pragma unroll
            for (int i = 0; i < 4; i++) {
                __half2 p0 = __floats2half2_rn(a[i * 8 + 0], a[i * 8 + 1]);
                __half2 p1 = __floats2half2_rn(a[i * 8 + 2], a[i * 8 + 3]);
                __half2 p2 = __floats2half2_rn(a[i * 8 + 4], a[i * 8 + 5]);
                __half2 p3 = __floats2half2_rn(a[i * 8 + 6], a[i * 8 + 7]);
                uint4 w;
                w.x = *(unsigned*)&p0; w.y = *(unsigned*)&p1;
                w.z = *(unsigned*)&p2; w.w = *(unsigned*)&p3;
                *(uint4*)(g_Ah + base + i * 8) = w;
            }
            *(float2*)&g_V[(size_t)node * 2] = make_float2(1.f, 0.f);
        }
    }
}

// ---------------------------------------------------------------- launch 1: single-kernel scan (decoupled lookback)
__global__ void k_scan(int n, int e) {
    int b = blockIdx.x, t = threadIdx.x;
    int base = b * SCAN_CHUNK + t * 4;
    int d0 = 0, d1 = 0, d2 = 0, d3 = 0;
    if (base + 0 < n) d0 = g_deg[base + 0];
    if (base + 1 < n) d1 = g_deg[base + 1];
    if (base + 2 < n) d2 = g_deg[base + 2];
    if (base + 3 < n) d3 = g_deg[base + 3];
    int tsum = d0 + d1 + d2 + d3;
    __shared__ int sc[1024];
    sc[t] = tsum; __syncthreads();
    for (int off = 1; off < 1024; off <<= 1) {
        int v = (t >= off) ? sc[t - off] : 0;
        __syncthreads();
        sc[t] += v;
        __syncthreads();
    }
    __shared__ int s_off;
    if (t == 0) {
        int agg = sc[1023];
        int off = 0;
        if (b == 0) {
            atomicExch(&g_scanstate[0], (agg << 2) | 2);
            g_rowptr[n] = e;
        } else {
            atomicExch(&g_scanstate[b], (agg << 2) | 1);
            int p = b - 1;
            while (p >= 0) {
                int s;
                do { s = atomicAdd(&g_scanstate[p], 0); } while ((s & 3) == 0);
                off += (s >> 2);
                if ((s & 3) == 2) break;
                p--;
            }
            atomicExch(&g_scanstate[b], ((off + agg) << 2) | 2);
        }
        s_off = off;
    }
    __syncthreads();
    int excl = sc[t] - tsum + s_off;
    int p0 = excl, p1 = excl + d0, p2 = p1 + d1, p3 = p2 + d2;
    if (base + 0 < n) { g_rowptr[base + 0] = p0; g_cursor[base + 0] = p0; }
    if (base + 1 < n) { g_rowptr[base + 1] = p1; g_cursor[base + 1] = p1; }
    if (base + 2 < n) { g_rowptr[base + 2] = p2; g_cursor[base + 2] = p2; }
    if (base + 3 < n) { g_rowptr[base + 3] = p3; g_cursor[base + 3] = p3; }
}

// ---------------------------------------------------------------- launch 2: scatter 16B edge records + state reset
__global__ __launch_bounds__(256) void k_scatter(
    const int* __restrict__ send, const int* __restrict__ recv,
    const float* __restrict__ mask, const float4* __restrict__ ef, int e, int n) {
    int gid = blockIdx.x * blockDim.x + threadIdx.x;
    int stride = gridDim.x * blockDim.x;
    for (int i = gid; i < e; i += stride) {
        int r = recv[i];
        r = min(max(r, 0), n - 1);
        int pos = atomicAdd(&g_cursor[r], 1);
        pos = min(max(pos, 0), EMAX - 1);      // defensive clamp (inert if CSR intact)
        float mk = mask[i];
        float4 f = ef[i];
        __half2 e01 = __floats2half2_rn(mk * f.x, mk * f.y);
        __half2 e23 = __floats2half2_rn(mk * f.z, mk * f.w);
        uint4 rec;
        rec.x = (unsigned)min(max(send[i], 0), n - 1);
        rec.y = __float_as_uint(mk);
        rec.z = *(unsigned*)&e01;
        rec.w = *(unsigned*)&e23;
        g_rec[pos] = rec;
    }
    // state reset for next call/replay: g_deg & g_scanstate already consumed
    // (launch 1); g_pooled & g_gst2[0] have no consumer until launch 3+.
    for (int i = gid; i < n; i += stride) g_deg[i] = 0;
    if (gid < MAXCHUNK) g_scanstate[gid] = 0;
    if (gid < NLAYER * HD) g_pooled[gid] = 0.f;
    if (gid < HD) g_gst2[0][gid] = 0.f;
}

// ---------------------------------------------------------------- launch 3 (PROFILED): hot SpMM h = relu(S @ A + D)
// Slim register budget: __launch_bounds__(256, 6) -> <=42 regs -> 75% occupancy.
template <bool FIRST>
__global__ __launch_bounds__(256, 6) void k_agg(
    const float* __restrict__ W2,   // W_msg[l] rows 34..37 (4x32)
    const float* __restrict__ bm,   // b_msg[l]
    int layer, int n, int e) {
    __shared__ float sW2[4][HD], sb[HD], spool[HD];
    int tid = threadIdx.x;
    if (tid < 4 * HD) sW2[tid >> 5][tid & 31] = W2[tid];
    if (tid < HD) { sb[tid] = bm[tid]; spool[tid] = 0.f; }
    __syncthreads();
    const unsigned nm1 = (unsigned)(n - 1);
    int lane = tid & 31;
    int sub = lane >> 2;          // edge slot 0..7
    int q   = lane & 3;           // column quarter: cols q*8 .. q*8+7
    int wpb = blockDim.x >> 5;
    int gw = blockIdx.x * wpb + (tid >> 5), nw = gridDim.x * wpb;
    for (int v = gw; v < n; v += nw) {
        int beg = g_rowptr[v], end = g_rowptr[v + 1];
        end = min(end, e); beg = max(min(beg, end), 0);   // defensive clamp
        // --- FIRST: per-receiver edge-feature sums, stored then reloaded in epilogue ---
        if (FIRST) {
            float4 cf = make_float4(0.f, 0.f, 0.f, 0.f);
            float cn = 0.f;
            for (int j = beg + lane; j < end; j += 32) {
                uint4 r = g_rec[j];
                float2 e01 = __half22float2(*(const __half2*)&r.z);
                float2 e23 = __half22float2(*(const __half2*)&r.w);
                cf.x += e01.x; cf.y += e01.y; cf.z += e23.x; cf.w += e23.y;
                cn += __uint_as_float(r.y);
            }
#pragma unroll
            for (int off = 16; off > 0; off >>= 1) {
                cf.x += __shfl_xor_sync(WARP_FULL, cf.x, off);
                cf.y += __shfl_xor_sync(WARP_FULL, cf.y, off);
                cf.z += __shfl_xor_sync(WARP_FULL, cf.z, off);
                cf.w += __shfl_xor_sync(WARP_FULL, cf.w, off);
                cn   += __shfl_xor_sync(WARP_FULL, cn, off);
            }
            if (lane == 0) {
                *(float4*)&g_Cfeat[(size_t)v * 4] = cf;
                g_Ccnt[v] = cn;
            }
            __syncwarp();   // make lane0's stores visible to lanes 1..3 in epilogue
        }
        // --- main edge loop: 8 edges/iter, 4 lanes/edge, record prefetch ---
        float acc[8];
#pragma unroll
        for (int i = 0; i < 8; i++) acc[i] = 0.f;
        int j = beg + sub;
        uint4 r = make_uint4(0u, 0u, 0u, 0u);
        if (j < end) r = g_rec[j];
        for (int base = beg; base < end; base += 8) {
            uint4 rc = r;
            int nj = base + 8 + sub;
            r = make_uint4(0u, 0u, 0u, 0u);
            if (nj < end) r = g_rec[nj];
            const uint4 a = *(const uint4*)(g_Ah + (size_t)min(rc.x, nm1) * HD + (q << 3));
            float cmk = __uint_as_float(rc.y);
            float2 f0 = __half22float2(*(const __half2*)&a.x);
            float2 f1 = __half22float2(*(const __half2*)&a.y);
            float2 f2 = __half22float2(*(const __half2*)&a.z);
            float2 f3 = __half22float2(*(const __half2*)&a.w);
            acc[0] += cmk * f0.x; acc[1] += cmk * f0.y;
            acc[2] += cmk * f1.x; acc[3] += cmk * f1.y;
            acc[4] += cmk * f2.x; acc[5] += cmk * f2.y;
            acc[6] += cmk * f3.x; acc[7] += cmk * f3.y;
        }
#pragma unroll
        for (int off = 4; off < 32; off <<= 1) {
#pragma unroll
            for (int i = 0; i < 8; i++)
                acc[i] += __shfl_xor_sync(WARP_FULL, acc[i], off);
        }
        if (sub == 0) {   // lanes 0..3: lane q owns cols q*8..q*8+7
            float4 cf = *(const float4*)&g_Cfeat[(size_t)v * 4];
            float cn = g_Ccnt[v];
            int c0 = q << 3;
            float hv[8];
#pragma unroll
            for (int i = 0; i < 8; i++) {
                int c = c0 + i;
                float t = acc[i] + cf.x * sW2[0][c] + cf.y * sW2[1][c] +
                          cf.z * sW2[2][c] + cf.w * sW2[3][c] + cn * sb[c];
                hv[i] = fmaxf(t, 0.f);
                atomicAdd(&spool[c], hv[i]);
            }
            float* hrow = g_h + (size_t)v * HD + c0;
            *(float4*)(hrow + 0) = make_float4(hv[0], hv[1], hv[2], hv[3]);
            *(float4*)(hrow + 4) = make_float4(hv[4], hv[5], hv[6], hv[7]);
        }
    }
    __syncthreads();
    if (tid < HD) atomicAdd(&g_pooled[layer * HD + tid], spool[tid]);
}

// ---------------------------------------------------------------- node update: thread-per-node, smem-staged
template <bool LAST>
__global__ __launch_bounds__(256) void k_upd(
    const float* __restrict__ Wg, const float* __restrict__ bg,
    const float* __restrict__ Wn, const float* __restrict__ bn,
    const float* __restrict__ Wo, const float* __restrict__ bo,
    const float* __restrict__ WmNext,
    float* __restrict__ out, int layer, float invn, int n) {
    __shared__ float sWn[HD * HD], sWm[34 * HD], sWo0[HD], sWo1[HD], gterm[HD], sgnew[HD];
    __shared__ float sh[TILE][HD + 1];
    int tid = threadIdx.x;
    for (int i = tid; i < HD * HD; i += 256) sWn[i] = Wn[i];   // rows 0..31 (h part)
    if (!LAST)
        for (int i = tid; i < 34 * HD; i += 256) sWm[i] = WmNext[i];
    if (tid < HD) {
        sWo0[tid] = Wo[tid * 2 + 0];
        sWo1[tid] = Wo[tid * 2 + 1];
        // inline supernode update (reads only pre-kernel state)
        float acc = bg[tid];
#pragma unroll
        for (int k = 0; k < HD; k++) acc += g_gst2[layer][k] * Wg[k * HD + tid];
#pragma unroll
        for (int k = 0; k < HD; k++)
            acc += (g_pooled[layer * HD + k] * invn) * Wg[(HD + k) * HD + tid];
        float gn = fmaxf(acc, 0.f);
        sgnew[tid] = gn;
        if (blockIdx.x == 0) g_gst2[layer + 1][tid] = gn;
    }
    __syncthreads();
    if (tid < HD) {
        float gt = bn[tid];
#pragma unroll
        for (int k = 0; k < HD; k++) gt += sgnew[k] * Wn[(HD + k) * HD + tid];
        gterm[tid] = gt;
    }
    float bo0 = bo[0], bo1 = bo[1];
    for (int tb = blockIdx.x * TILE; tb < n; tb += gridDim.x * TILE) {
        int nt = min(TILE, n - tb);
        __syncthreads();   // also orders gterm/sgnew writes before reads below
        for (int i = tid; i < nt * HD; i += 256)
            sh[i >> 5][i & 31] = g_h[(size_t)tb * HD + i];
        __syncthreads();
        int node = tb + tid;
        if (tid < nt) {
            float acc[HD];
#pragma unroll
            for (int c = 0; c < HD; c++) acc[c] = gterm[c];
#pragma unroll
            for (int k = 0; k < HD; k++) {
                float hk = sh[tid][k];
#pragma unroll
                for (int c = 0; c < HD; c++) acc[c] += hk * sWn[k * HD + c];
            }
            float p0 = 0.f, p1 = 0.f;
#pragma unroll
            for (int c = 0; c < HD; c++) {
                acc[c] = fmaxf(acc[c], 0.f);
                p0 += acc[c] * sWo0[c];
                p1 += acc[c] * sWo1[c];
            }
            float2 Vold = *(const float2*)&g_V[(size_t)node * 2];
            float V0 = Vold.x + p0 + bo0;
            float V1 = Vold.y + p1 + bo1;
            if (LAST) {
                *(float2*)&out[(size_t)node * 2] = make_float2(V0, V1);
            } else {
                *(float2*)&g_V[(size_t)node * 2] = make_float2(V0, V1);
                float a2[HD];
#pragma unroll
                for (int c = 0; c < HD; c++) a2[c] = V0 * sWm[c] + V1 * sWm[HD + c];
#pragma unroll
                for (int k = 0; k < HD; k++) {
                    float hk = acc[k];
#pragma unroll
                    for (int c = 0; c < HD; c++) a2[c] += hk * sWm[(2 + k) * HD + c];
                }
                size_t base = (size_t)node * HD;
#pragma unroll
                for (int i = 0; i < 4; i++) {
                    __half2 h0 = __floats2half2_rn(a2[i * 8 + 0], a2[i * 8 + 1]);
                    __half2 h1 = __floats2half2_rn(a2[i * 8 + 2], a2[i * 8 + 3]);
                    __half2 h2 = __floats2half2_rn(a2[i * 8 + 4], a2[i * 8 + 5]);
                    __half2 h3 = __floats2half2_rn(a2[i * 8 + 6], a2[i * 8 + 7]);
                    uint4 w;
                    w.x = *(unsigned*)&h0; w.y = *(unsigned*)&h1;
                    w.z = *(unsigned*)&h2; w.w = *(unsigned*)&h3;
                    *(uint4*)(g_Ah + base + i * 8) = w;
                }
            }
        }
    }
}

// ---------------------------------------------------------------- launcher
extern "C" void kernel_launch(void* const* d_in, const int* in_sizes, int n_in,
                              void* d_out, int out_size) {
    const float* PQ    = (const float*)d_in[0];
    const int*   send  = (const int*)d_in[1];
    const int*   recv  = (const int*)d_in[2];
    const float* ef    = (const float*)d_in[3];
    const float* emask = (const float*)d_in[4];
    const float* Win   = (const float*)d_in[5];
    const float* bin   = (const float*)d_in[6];
    const float* Wmsg  = (const float*)d_in[7];
    const float* bmsg  = (const float*)d_in[8];
    const float* Wg    = (const float*)d_in[9];
    const float* bg    = (const float*)d_in[10];
    const float* Wn    = (const float*)d_in[11];
    const float* bn    = (const float*)d_in[12];
    const float* Wo    = (const float*)d_in[13];
    const float* bo    = (const float*)d_in[14];
    float* out = (float*)d_out;

    int n = in_sizes[0] / 2;
    int e = in_sizes[1];

    const int PB = 1184;
    const int EB = 2048;
    int nch = (n + SCAN_CHUNK - 1) / SCAN_CHUNK;
    int upb = (n + TILE - 1) / TILE;

    // launch 0..2: CSR build + init (+ state reset inside k_scatter)
    k_histinit<<<PB, 256>>>(recv, e, (const float2*)PQ, Win, bin, Wmsg, n);
    k_scan<<<nch, 1024>>>(n, e);
    k_scatter<<<EB, 256>>>(send, recv, emask, (const float4*)ef, e, n);

    float invn = 1.f / (float)n;
    for (int l = 0; l < NLAYER; l++) {
        // launch 3 (layer 0) is the ncu-profiled launch
        if (l == 0)
            k_agg<true><<<PB, 256>>>(Wmsg + (size_t)(l * 38 + 34) * HD, bmsg + l * HD, l, n, e);
        else
            k_agg<false><<<PB, 256>>>(Wmsg + (size_t)(l * 38 + 34) * HD, bmsg + l * HD, l, n, e);
        if (l < NLAYER - 1)
            k_upd<false><<<upb, 256>>>(Wg + (size_t)l * 64 * HD, bg + l * HD,
                                       Wn + (size_t)l * 64 * HD, bn + l * HD,
                                       Wo + (size_t)l * HD * 2, bo + l * 2,
                                       Wmsg + (size_t)(l + 1) * 38 * HD, out, l, invn, n);
        else
            k_upd<true><<<upb, 256>>>(Wg + (size_t)l * 64 * HD, bg + l * HD,
                                      Wn + (size_t)l * 64 * HD, bn + l * HD,
                                      Wo + (size_t)l * HD * 2, bo + l * 2,
                                      nullptr, out, l, invn, n);
    }
}

// round 13
// speedup vs baseline: 1.1106x; 1.1106x over previous
#include <cuda_runtime.h>
#include <cuda_fp16.h>

#define WARP_FULL 0xFFFFFFFFu

namespace {
constexpr int NMAX = 100000;
constexpr int EMAX = 3200000;
constexpr int HD = 32;
constexpr int NLAYER = 3;
constexpr int SCAN_CHUNK = 4096;   // 1024 threads * 4 items
constexpr int MAXCHUNK = 64;
constexpr int TILE = 256;          // nodes per block-tile in thread-per-node kernels
}

// ---- persistent device scratch (module-load zero-init; no runtime allocs) ----
__device__ __align__(128) __half g_Ah[(size_t)NMAX * HD];   // fp16 message precursor rows (64 B/row)
__device__ __align__(128) float  g_h[(size_t)NMAX * HD];
__device__ __align__(16)  float  g_V[(size_t)NMAX * 2];
__device__ __align__(16)  float  g_Cfeat[(size_t)NMAX * 4];
__device__ float g_Ccnt[NMAX];
__device__ int   g_deg[NMAX];        // zero at entry (reset by k_scatter of previous call)
__device__ int   g_rowptr[NMAX + 1];
__device__ int   g_cursor[NMAX];
// one 16-byte record per edge, CSR order: {send, mask bits, half2(mask*ef01), half2(mask*ef23)}
__device__ __align__(128) uint4 g_rec[EMAX];
__device__ float g_pooled[NLAYER * HD];           // zero at entry (reset by k_scatter)
__device__ float g_gst2[NLAYER + 1][HD];          // gst2[0] zero at entry (reset by k_scatter)
__device__ int   g_scanstate[MAXCHUNK];           // zero at entry (reset by k_scatter)

// ---------------------------------------------------------------- launch 0: histogram + A0/V init (thread-per-node)
__global__ __launch_bounds__(256) void k_histinit(
    const int* __restrict__ recv, int e,
    const float2* __restrict__ PQ, const float* __restrict__ Win,
    const float* __restrict__ bin, const float* __restrict__ Wmsg0, int n) {
    __shared__ float sWin0[HD], sWin1[HD], sbin[HD], sWm[34 * HD];
    int tid = threadIdx.x;
    if (tid < HD) { sWin0[tid] = Win[tid]; sWin1[tid] = Win[HD + tid]; sbin[tid] = bin[tid]; }
    for (int i = tid; i < 34 * HD; i += 256) sWm[i] = Wmsg0[i];
    __syncthreads();

    // phase 1: receiver histogram (index clamped)
    int gid = blockIdx.x * 256 + tid, gs = gridDim.x * 256;
    for (int i = gid; i < e; i += gs) {
        int r = recv[i];
        r = min(max(r, 0), n - 1);
        atomicAdd(&g_deg[r], 1);
    }

    // phase 2: thread-per-node A0 = [1,0,h0] @ Wmsg0[:34]; V init
    for (int tb = blockIdx.x * TILE; tb < n; tb += gridDim.x * TILE) {
        int node = tb + tid;
        if (node < n) {
            float2 pq = PQ[node];
            float h0[HD];
#pragma unroll
            for (int c = 0; c < HD; c++)
                h0[c] = pq.x * sWin0[c] + pq.y * sWin1[c] + sbin[c];
            float a[HD];
#pragma unroll
            for (int c = 0; c < HD; c++) a[c] = sWm[c];   // V = (1,0): row 0
#pragma unroll
            for (int k = 0; k < HD; k++) {
                float hk = h0[k];
#pragma unroll
                for (int c = 0; c < HD; c++) a[c] += hk * sWm[(2 + k) * HD + c];
            }
            size_t base = (size_t)node * HD;
#pragma unroll
            for (int i = 0; i < 4; i++) {
                __half2 p0 = __floats2half2_rn(a[i * 8 + 0], a[i * 8 + 1]);
                __half2 p1 = __floats2half2_rn(a[i * 8 + 2], a[i * 8 + 3]);
                __half2 p2 = __floats2half2_rn(a[i * 8 + 4], a[i * 8 + 5]);
                __half2 p3 = __floats2half2_rn(a[i * 8 + 6], a[i * 8 + 7]);
                uint4 w;
                w.x = *(unsigned*)&p0; w.y = *(unsigned*)&p1;
                w.z = *(unsigned*)&p2; w.w = *(unsigned*)&p3;
                *(uint4*)(g_Ah + base + i * 8) = w;
            }
            *(float2*)&g_V[(size_t)node * 2] = make_float2(1.f, 0.f);
        }
    }
}

// ---------------------------------------------------------------- launch 1: single-kernel scan (decoupled lookback)
__global__ void k_scan(int n, int e) {
    int b = blockIdx.x, t = threadIdx.x;
    int base = b * SCAN_CHUNK + t * 4;
    int d0 = 0, d1 = 0, d2 = 0, d3 = 0;
    if (base + 0 < n) d0 = g_deg[base + 0];
    if (base + 1 < n) d1 = g_deg[base + 1];
    if (base + 2 < n) d2 = g_deg[base + 2];
    if (base + 3 < n) d3 = g_deg[base + 3];
    int tsum = d0 + d1 + d2 + d3;
    __shared__ int sc[1024];
    sc[t] = tsum; __syncthreads();
    for (int off = 1; off < 1024; off <<= 1) {
        int v = (t >= off) ? sc[t - off] : 0;
        __syncthreads();
        sc[t] += v;
        __syncthreads();
    }
    __shared__ int s_off;
    if (t == 0) {
        int agg = sc[1023];
        int off = 0;
        if (b == 0) {
            atomicExch(&g_scanstate[0], (agg << 2) | 2);
            g_rowptr[n] = e;
        } else {
            atomicExch(&g_scanstate[b], (agg << 2) | 1);
            int p = b - 1;
            while (p >= 0) {
                int s;
                do { s = atomicAdd(&g_scanstate[p], 0); } while ((s & 3) == 0);
                off += (s >> 2);
                if ((s & 3) == 2) break;
                p--;
            }
            atomicExch(&g_scanstate[b], ((off + agg) << 2) | 2);
        }
        s_off = off;
    }
    __syncthreads();
    int excl = sc[t] - tsum + s_off;
    int p0 = excl, p1 = excl + d0, p2 = p1 + d1, p3 = p2 + d2;
    if (base + 0 < n) { g_rowptr[base + 0] = p0; g_cursor[base + 0] = p0; }
    if (base + 1 < n) { g_rowptr[base + 1] = p1; g_cursor[base + 1] = p1; }
    if (base + 2 < n) { g_rowptr[base + 2] = p2; g_cursor[base + 2] = p2; }
    if (base + 3 < n) { g_rowptr[base + 3] = p3; g_cursor[base + 3] = p3; }
}

// ---------------------------------------------------------------- launch 2: scatter 16B edge records + state reset
__global__ __launch_bounds__(256) void k_scatter(
    const int* __restrict__ send, const int* __restrict__ recv,
    const float* __restrict__ mask, const float4* __restrict__ ef, int e, int n) {
    int gid = blockIdx.x * blockDim.x + threadIdx.x;
    int stride = gridDim.x * blockDim.x;
    for (int i = gid; i < e; i += stride) {
        int r = recv[i];
        r = min(max(r, 0), n - 1);
        int pos = atomicAdd(&g_cursor[r], 1);
        pos = min(max(pos, 0), EMAX - 1);      // defensive clamp (inert if CSR intact)
        float mk = mask[i];
        float4 f = ef[i];
        __half2 e01 = __floats2half2_rn(mk * f.x, mk * f.y);
        __half2 e23 = __floats2half2_rn(mk * f.z, mk * f.w);
        uint4 rec;
        rec.x = (unsigned)min(max(send[i], 0), n - 1);
        rec.y = __float_as_uint(mk);
        rec.z = *(unsigned*)&e01;
        rec.w = *(unsigned*)&e23;
        g_rec[pos] = rec;
    }
    // state reset for next call/replay: g_deg & g_scanstate already consumed
    // (launch 1); g_pooled & g_gst2[0] have no consumer until launch 3+.
    for (int i = gid; i < n; i += stride) g_deg[i] = 0;
    if (gid < MAXCHUNK) g_scanstate[gid] = 0;
    if (gid < NLAYER * HD) g_pooled[gid] = 0.f;
    if (gid < HD) g_gst2[0][gid] = 0.f;
}

// ---------------------------------------------------------------- launch 3 (PROFILED): hot SpMM h = relu(S @ A + D)
// R11 configuration (pacc regs, depth-2 pipeline, no min-blocks clamp) +
// FIRST folds Cfeat/Ccnt accumulation into the main edge loop (no pre-pass).
template <bool FIRST>
__global__ __launch_bounds__(256) void k_agg(
    const float* __restrict__ W2,   // W_msg[l] rows 34..37 (4x32)
    const float* __restrict__ bm,   // b_msg[l]
    int layer, int n, int e) {
    __shared__ float sW2[4][HD], sb[HD], spool[HD];
    int tid = threadIdx.x;
    if (tid < 4 * HD) sW2[tid >> 5][tid & 31] = W2[tid];
    if (tid < HD) { sb[tid] = bm[tid]; spool[tid] = 0.f; }
    __syncthreads();
    const unsigned nm1 = (unsigned)(n - 1);
    int lane = tid & 31;
    int sub = lane >> 2;          // edge slot 0..7
    int q   = lane & 3;           // column quarter: cols q*8 .. q*8+7
    int wpb = blockDim.x >> 5;
    int gw = blockIdx.x * wpb + (tid >> 5), nw = gridDim.x * wpb;
    float pacc[8];
#pragma unroll
    for (int i = 0; i < 8; i++) pacc[i] = 0.f;
    for (int v = gw; v < n; v += nw) {
        int beg = g_rowptr[v], end = g_rowptr[v + 1];
        end = min(end, e); beg = max(min(beg, end), 0);   // defensive clamp
        // --- main edge loop: 8 edges/iter, 4 lanes/edge, depth-2 gather pipeline ---
        float acc[8];
#pragma unroll
        for (int i = 0; i < 8; i++) acc[i] = 0.f;
        float cfacc = 0.f, cnacc = 0.f;    // FIRST only: lane q's ef component / cnt
        int j0 = beg + sub;
        uint4 r0 = make_uint4(0u, 0u, 0u, 0u), r1 = make_uint4(0u, 0u, 0u, 0u);
        if (j0 < end) r0 = g_rec[j0];
        uint4 a0 = *(const uint4*)(g_Ah + (size_t)min(r0.x, nm1) * HD + (q << 3));
        if (j0 + 8 < end) r1 = g_rec[j0 + 8];
        uint4 a1 = *(const uint4*)(g_Ah + (size_t)min(r1.x, nm1) * HD + (q << 3));
        for (int base = beg; base < end; base += 8) {
            float cmk = __uint_as_float(r0.y);
            uint4 a = a0;
            if (FIRST) {
                // lane q accumulates ef component q of its edge; q==0 also counts mask.
                // zeroed records (j >= end) contribute 0 to every component.
                __half2 hz = *(const __half2*)&r0.z;
                __half2 hw = *(const __half2*)&r0.w;
                float comp = (q == 0) ? __low2float(hz) :
                             (q == 1) ? __high2float(hz) :
                             (q == 2) ? __low2float(hw) : __high2float(hw);
                cfacc += comp;
                if (q == 0) cnacc += cmk;
            }
            r0 = r1; a0 = a1;
            int nj = base + 16 + sub;
            r1 = make_uint4(0u, 0u, 0u, 0u);
            if (nj < end) r1 = g_rec[nj];
            a1 = *(const uint4*)(g_Ah + (size_t)min(r1.x, nm1) * HD + (q << 3));
            float2 f0 = __half22float2(*(const __half2*)&a.x);
            float2 f1 = __half22float2(*(const __half2*)&a.y);
            float2 f2 = __half22float2(*(const __half2*)&a.z);
            float2 f3 = __half22float2(*(const __half2*)&a.w);
            acc[0] += cmk * f0.x; acc[1] += cmk * f0.y;
            acc[2] += cmk * f1.x; acc[3] += cmk * f1.y;
            acc[4] += cmk * f2.x; acc[5] += cmk * f2.y;
            acc[6] += cmk * f3.x; acc[7] += cmk * f3.y;
        }
        // reduce across the 8 edge slots (lanes with same q, strides 4/8/16);
        // the same reduction collapses cfacc/cnacc onto lanes 0..3.
#pragma unroll
        for (int off = 4; off < 32; off <<= 1) {
#pragma unroll
            for (int i = 0; i < 8; i++)
                acc[i] += __shfl_xor_sync(WARP_FULL, acc[i], off);
            if (FIRST) {
                cfacc += __shfl_xor_sync(WARP_FULL, cfacc, off);
                cnacc += __shfl_xor_sync(WARP_FULL, cnacc, off);
            }
        }
        // fetch/broadcast Cfeat + Ccnt
        float4 cf;
        float cn;
        if (FIRST) {
            cf.x = __shfl_sync(WARP_FULL, cfacc, 0);
            cf.y = __shfl_sync(WARP_FULL, cfacc, 1);
            cf.z = __shfl_sync(WARP_FULL, cfacc, 2);
            cf.w = __shfl_sync(WARP_FULL, cfacc, 3);
            cn   = __shfl_sync(WARP_FULL, cnacc, 0);
            if (lane == 0) {
                *(float4*)&g_Cfeat[(size_t)v * 4] = cf;
                g_Ccnt[v] = cn;
            }
        } else {
            cf = *(const float4*)&g_Cfeat[(size_t)v * 4];
            cn = g_Ccnt[v];
        }
        if (sub == 0) {   // lanes 0..3: lane q owns cols q*8..q*8+7
            int c0 = q << 3;
            float hv[8];
#pragma unroll
            for (int i = 0; i < 8; i++) {
                int c = c0 + i;
                float t = acc[i] + cf.x * sW2[0][c] + cf.y * sW2[1][c] +
                          cf.z * sW2[2][c] + cf.w * sW2[3][c] + cn * sb[c];
                hv[i] = fmaxf(t, 0.f);
                pacc[i] += hv[i];
            }
            float* hrow = g_h + (size_t)v * HD + c0;
            *(float4*)(hrow + 0) = make_float4(hv[0], hv[1], hv[2], hv[3]);
            *(float4*)(hrow + 4) = make_float4(hv[4], hv[5], hv[6], hv[7]);
        }
    }
    if ((lane >> 2) == 0) {
        int c0 = q << 3;
#pragma unroll
        for (int i = 0; i < 8; i++) atomicAdd(&spool[c0 + i], pacc[i]);
    }
    __syncthreads();
    if (tid < HD) atomicAdd(&g_pooled[layer * HD + tid], spool[tid]);
}

// ---------------------------------------------------------------- node update: thread-per-node, smem-staged
template <bool LAST>
__global__ __launch_bounds__(256) void k_upd(
    const float* __restrict__ Wg, const float* __restrict__ bg,
    const float* __restrict__ Wn, const float* __restrict__ bn,
    const float* __restrict__ Wo, const float* __restrict__ bo,
    const float* __restrict__ WmNext,
    float* __restrict__ out, int layer, float invn, int n) {
    __shared__ float sWn[HD * HD], sWm[34 * HD], sWo0[HD], sWo1[HD], gterm[HD], sgnew[HD];
    __shared__ float sh[TILE][HD + 1];
    int tid = threadIdx.x;
    for (int i = tid; i < HD * HD; i += 256) sWn[i] = Wn[i];   // rows 0..31 (h part)
    if (!LAST)
        for (int i = tid; i < 34 * HD; i += 256) sWm[i] = WmNext[i];
    if (tid < HD) {
        sWo0[tid] = Wo[tid * 2 + 0];
        sWo1[tid] = Wo[tid * 2 + 1];
        // inline supernode update (reads only pre-kernel state)
        float acc = bg[tid];
#pragma unroll
        for (int k = 0; k < HD; k++) acc += g_gst2[layer][k] * Wg[k * HD + tid];
#pragma unroll
        for (int k = 0; k < HD; k++)
            acc += (g_pooled[layer * HD + k] * invn) * Wg[(HD + k) * HD + tid];
        float gn = fmaxf(acc, 0.f);
        sgnew[tid] = gn;
        if (blockIdx.x == 0) g_gst2[layer + 1][tid] = gn;
    }
    __syncthreads();
    if (tid < HD) {
        float gt = bn[tid];
#pragma unroll
        for (int k = 0; k < HD; k++) gt += sgnew[k] * Wn[(HD + k) * HD + tid];
        gterm[tid] = gt;
    }
    float bo0 = bo[0], bo1 = bo[1];
    for (int tb = blockIdx.x * TILE; tb < n; tb += gridDim.x * TILE) {
        int nt = min(TILE, n - tb);
        __syncthreads();   // also orders gterm/sgnew writes before reads below
        for (int i = tid; i < nt * HD; i += 256)
            sh[i >> 5][i & 31] = g_h[(size_t)tb * HD + i];
        __syncthreads();
        int node = tb + tid;
        if (tid < nt) {
            float acc[HD];
#pragma unroll
            for (int c = 0; c < HD; c++) acc[c] = gterm[c];
#pragma unroll
            for (int k = 0; k < HD; k++) {
                float hk = sh[tid][k];
#pragma unroll
                for (int c = 0; c < HD; c++) acc[c] += hk * sWn[k * HD + c];
            }
            float p0 = 0.f, p1 = 0.f;
#pragma unroll
            for (int c = 0; c < HD; c++) {
                acc[c] = fmaxf(acc[c], 0.f);
                p0 += acc[c] * sWo0[c];
                p1 += acc[c] * sWo1[c];
            }
            float2 Vold = *(const float2*)&g_V[(size_t)node * 2];
            float V0 = Vold.x + p0 + bo0;
            float V1 = Vold.y + p1 + bo1;
            if (LAST) {
                *(float2*)&out[(size_t)node * 2] = make_float2(V0, V1);
            } else {
                *(float2*)&g_V[(size_t)node * 2] = make_float2(V0, V1);
                float a2[HD];
#pragma unroll
                for (int c = 0; c < HD; c++) a2[c] = V0 * sWm[c] + V1 * sWm[HD + c];
#pragma unroll
                for (int k = 0; k < HD; k++) {
                    float hk = acc[k];
#pragma unroll
                    for (int c = 0; c < HD; c++) a2[c] += hk * sWm[(2 + k) * HD + c];
                }
                size_t base = (size_t)node * HD;
#pragma unroll
                for (int i = 0; i < 4; i++) {
                    __half2 h0 = __floats2half2_rn(a2[i * 8 + 0], a2[i * 8 + 1]);
                    __half2 h1 = __floats2half2_rn(a2[i * 8 + 2], a2[i * 8 + 3]);
                    __half2 h2 = __floats2half2_rn(a2[i * 8 + 4], a2[i * 8 + 5]);
                    __half2 h3 = __floats2half2_rn(a2[i * 8 + 6], a2[i * 8 + 7]);
                    uint4 w;
                    w.x = *(unsigned*)&h0; w.y = *(unsigned*)&h1;
                    w.z = *(unsigned*)&h2; w.w = *(unsigned*)&h3;
                    *(uint4*)(g_Ah + base + i * 8) = w;
                }
            }
        }
    }
}

// ---------------------------------------------------------------- launcher
extern "C" void kernel_launch(void* const* d_in, const int* in_sizes, int n_in,
                              void* d_out, int out_size) {
    const float* PQ    = (const float*)d_in[0];
    const int*   send  = (const int*)d_in[1];
    const int*   recv  = (const int*)d_in[2];
    const float* ef    = (const float*)d_in[3];
    const float* emask = (const float*)d_in[4];
    const float* Win   = (const float*)d_in[5];
    const float* bin   = (const float*)d_in[6];
    const float* Wmsg  = (const float*)d_in[7];
    const float* bmsg  = (const float*)d_in[8];
    const float* Wg    = (const float*)d_in[9];
    const float* bg    = (const float*)d_in[10];
    const float* Wn    = (const float*)d_in[11];
    const float* bn    = (const float*)d_in[12];
    const float* Wo    = (const float*)d_in[13];
    const float* bo    = (const float*)d_in[14];
    float* out = (float*)d_out;

    int n = in_sizes[0] / 2;
    int e = in_sizes[1];

    const int PB = 1184;
    const int EB = 2048;
    int nch = (n + SCAN_CHUNK - 1) / SCAN_CHUNK;
    int upb = (n + TILE - 1) / TILE;

    // launch 0..2: CSR build + init (+ state reset inside k_scatter)
    k_histinit<<<PB, 256>>>(recv, e, (const float2*)PQ, Win, bin, Wmsg, n);
    k_scan<<<nch, 1024>>>(n, e);
    k_scatter<<<EB, 256>>>(send, recv, emask, (const float4*)ef, e, n);

    float invn = 1.f / (float)n;
    for (int l = 0; l < NLAYER; l++) {
        // launch 3 (layer 0) is the ncu-profiled launch
        if (l == 0)
            k_agg<true><<<PB, 256>>>(Wmsg + (size_t)(l * 38 + 34) * HD, bmsg + l * HD, l, n, e);
        else
            k_agg<false><<<PB, 256>>>(Wmsg + (size_t)(l * 38 + 34) * HD, bmsg + l * HD, l, n, e);
        if (l < NLAYER - 1)
            k_upd<false><<<upb, 256>>>(Wg + (size_t)l * 64 * HD, bg + l * HD,
                                       Wn + (size_t)l * 64 * HD, bn + l * HD,
                                       Wo + (size_t)l * HD * 2, bo + l * 2,
                                       Wmsg + (size_t)(l + 1) * 38 * HD, out, l, invn, n);
        else
            k_upd<true><<<upb, 256>>>(Wg + (size_t)l * 64 * HD, bg + l * HD,
                                      Wn + (size_t)l * 64 * HD, bn + l * HD,
                                      Wo + (size_t)l * HD * 2, bo + l * 2,
                                      nullptr, out, l, invn, n);
    }
}

// round 14
// speedup vs baseline: 1.1383x; 1.0250x over previous
#include <cuda_runtime.h>
#include <cuda_fp16.h>

#define WARP_FULL 0xFFFFFFFFu

namespace {
constexpr int NMAX = 100000;
constexpr int EMAX = 3200000;
constexpr int HD = 32;
constexpr int NLAYER = 3;
constexpr int SCAN_CHUNK = 4096;   // 1024 threads * 4 items
constexpr int MAXCHUNK = 64;
constexpr int TILE = 256;          // nodes per block-tile in thread-per-node kernels
}

// ---- persistent device scratch (module-load zero-init; no runtime allocs) ----
__device__ __align__(128) __half g_Ah[(size_t)NMAX * HD];   // fp16 message precursor rows (64 B/row)
__device__ __align__(128) float  g_h[(size_t)NMAX * HD];
__device__ __align__(16)  float  g_V[(size_t)NMAX * 2];
__device__ __align__(16)  float  g_Cfeat[(size_t)NMAX * 4];
__device__ float g_Ccnt[NMAX];
__device__ int   g_deg[NMAX];        // zero at entry (reset by k_scatter of previous call)
__device__ int   g_rowptr[NMAX + 1];
__device__ int   g_cursor[NMAX];
// one 16-byte record per edge, CSR order: {send, mask bits, half2(mask*ef01), half2(mask*ef23)}
__device__ __align__(128) uint4 g_rec[EMAX];
__device__ float g_pooled[NLAYER * HD];           // zero at entry (reset by k_scatter)
__device__ float g_gst2[NLAYER + 1][HD];          // gst2[0] zero at entry (reset by k_scatter)
__device__ int   g_scanstate[MAXCHUNK];           // zero at entry (reset by k_scatter)

// ---------------------------------------------------------------- launch 0: histogram + A0/V init (thread-per-node)
__global__ __launch_bounds__(256) void k_histinit(
    const int* __restrict__ recv, int e,
    const float2* __restrict__ PQ, const float* __restrict__ Win,
    const float* __restrict__ bin, const float* __restrict__ Wmsg0, int n) {
    __shared__ float sWin0[HD], sWin1[HD], sbin[HD], sWm[34 * HD];
    int tid = threadIdx.x;
    if (tid < HD) { sWin0[tid] = Win[tid]; sWin1[tid] = Win[HD + tid]; sbin[tid] = bin[tid]; }
    for (int i = tid; i < 34 * HD; i += 256) sWm[i] = Wmsg0[i];
    __syncthreads();

    // phase 1: receiver histogram (index clamped)
    int gid = blockIdx.x * 256 + tid, gs = gridDim.x * 256;
    for (int i = gid; i < e; i += gs) {
        int r = recv[i];
        r = min(max(r, 0), n - 1);
        atomicAdd(&g_deg[r], 1);
    }

    // phase 2: thread-per-node A0 = [1,0,h0] @ Wmsg0[:34]; V init
    for (int tb = blockIdx.x * TILE; tb < n; tb += gridDim.x * TILE) {
        int node = tb + tid;
        if (node < n) {
            float2 pq = PQ[node];
            float h0[HD];
#pragma unroll
            for (int c = 0; c < HD; c++)
                h0[c] = pq.x * sWin0[c] + pq.y * sWin1[c] + sbin[c];
            float a[HD];
#pragma unroll
            for (int c = 0; c < HD; c++) a[c] = sWm[c];   // V = (1,0): row 0
#pragma unroll
            for (int k = 0; k < HD; k++) {
                float hk = h0[k];
#pragma unroll
                for (int c = 0; c < HD; c++) a[c] += hk * sWm[(2 + k) * HD + c];
            }
            size_t base = (size_t)node * HD;
#pragma unroll
            for (int i = 0; i < 4; i++) {
                __half2 p0 = __floats2half2_rn(a[i * 8 + 0], a[i * 8 + 1]);
                __half2 p1 = __floats2half2_rn(a[i * 8 + 2], a[i * 8 + 3]);
                __half2 p2 = __floats2half2_rn(a[i * 8 + 4], a[i * 8 + 5]);
                __half2 p3 = __floats2half2_rn(a[i * 8 + 6], a[i * 8 + 7]);
                uint4 w;
                w.x = *(unsigned*)&p0; w.y = *(unsigned*)&p1;
                w.z = *(unsigned*)&p2; w.w = *(unsigned*)&p3;
                *(uint4*)(g_Ah + base + i * 8) = w;
            }
            *(float2*)&g_V[(size_t)node * 2] = make_float2(1.f, 0.f);
        }
    }
}

// ---------------------------------------------------------------- launch 1: single-kernel scan (decoupled lookback)
__global__ void k_scan(int n, int e) {
    int b = blockIdx.x, t = threadIdx.x;
    int base = b * SCAN_CHUNK + t * 4;
    int d0 = 0, d1 = 0, d2 = 0, d3 = 0;
    if (base + 0 < n) d0 = g_deg[base + 0];
    if (base + 1 < n) d1 = g_deg[base + 1];
    if (base + 2 < n) d2 = g_deg[base + 2];
    if (base + 3 < n) d3 = g_deg[base + 3];
    int tsum = d0 + d1 + d2 + d3;
    __shared__ int sc[1024];
    sc[t] = tsum; __syncthreads();
    for (int off = 1; off < 1024; off <<= 1) {
        int v = (t >= off) ? sc[t - off] : 0;
        __syncthreads();
        sc[t] += v;
        __syncthreads();
    }
    __shared__ int s_off;
    if (t == 0) {
        int agg = sc[1023];
        int off = 0;
        if (b == 0) {
            atomicExch(&g_scanstate[0], (agg << 2) | 2);
            g_rowptr[n] = e;
        } else {
            atomicExch(&g_scanstate[b], (agg << 2) | 1);
            int p = b - 1;
            while (p >= 0) {
                int s;
                do { s = atomicAdd(&g_scanstate[p], 0); } while ((s & 3) == 0);
                off += (s >> 2);
                if ((s & 3) == 2) break;
                p--;
            }
            atomicExch(&g_scanstate[b], ((off + agg) << 2) | 2);
        }
        s_off = off;
    }
    __syncthreads();
    int excl = sc[t] - tsum + s_off;
    int p0 = excl, p1 = excl + d0, p2 = p1 + d1, p3 = p2 + d2;
    if (base + 0 < n) { g_rowptr[base + 0] = p0; g_cursor[base + 0] = p0; }
    if (base + 1 < n) { g_rowptr[base + 1] = p1; g_cursor[base + 1] = p1; }
    if (base + 2 < n) { g_rowptr[base + 2] = p2; g_cursor[base + 2] = p2; }
    if (base + 3 < n) { g_rowptr[base + 3] = p3; g_cursor[base + 3] = p3; }
}

// ---------------------------------------------------------------- launch 2: scatter 16B edge records + state reset
__global__ __launch_bounds__(256) void k_scatter(
    const int* __restrict__ send, const int* __restrict__ recv,
    const float* __restrict__ mask, const float4* __restrict__ ef, int e, int n) {
    int gid = blockIdx.x * blockDim.x + threadIdx.x;
    int stride = gridDim.x * blockDim.x;
    for (int i = gid; i < e; i += stride) {
        int r = recv[i];
        r = min(max(r, 0), n - 1);
        int pos = atomicAdd(&g_cursor[r], 1);
        pos = min(max(pos, 0), EMAX - 1);      // defensive clamp (inert if CSR intact)
        float mk = mask[i];
        float4 f = ef[i];
        __half2 e01 = __floats2half2_rn(mk * f.x, mk * f.y);
        __half2 e23 = __floats2half2_rn(mk * f.z, mk * f.w);
        uint4 rec;
        rec.x = (unsigned)min(max(send[i], 0), n - 1);
        rec.y = __float_as_uint(mk);
        rec.z = *(unsigned*)&e01;
        rec.w = *(unsigned*)&e23;
        g_rec[pos] = rec;
    }
    // state reset for next call/replay: g_deg & g_scanstate already consumed
    // (launch 1); g_pooled & g_gst2[0] have no consumer until launch 3+.
    for (int i = gid; i < n; i += stride) g_deg[i] = 0;
    if (gid < MAXCHUNK) g_scanstate[gid] = 0;
    if (gid < NLAYER * HD) g_pooled[gid] = 0.f;
    if (gid < HD) g_gst2[0][gid] = 0.f;
}

// ---------------------------------------------------------------- launch 3 (PROFILED): hot SpMM h = relu(S @ A + D)
// R11 configuration (pacc regs, cfeat pre-pass for FIRST) with DEPTH-3 pipeline.
template <bool FIRST>
__global__ __launch_bounds__(256) void k_agg(
    const float* __restrict__ W2,   // W_msg[l] rows 34..37 (4x32)
    const float* __restrict__ bm,   // b_msg[l]
    int layer, int n, int e) {
    __shared__ float sW2[4][HD], sb[HD], spool[HD];
    int tid = threadIdx.x;
    if (tid < 4 * HD) sW2[tid >> 5][tid & 31] = W2[tid];
    if (tid < HD) { sb[tid] = bm[tid]; spool[tid] = 0.f; }
    __syncthreads();
    const unsigned nm1 = (unsigned)(n - 1);
    int lane = tid & 31;
    int sub = lane >> 2;          // edge slot 0..7
    int q   = lane & 3;           // column quarter: cols q*8 .. q*8+7
    int wpb = blockDim.x >> 5;
    int gw = blockIdx.x * wpb + (tid >> 5), nw = gridDim.x * wpb;
    float pacc[8];
#pragma unroll
    for (int i = 0; i < 8; i++) pacc[i] = 0.f;
    for (int v = gw; v < n; v += nw) {
        int beg = g_rowptr[v], end = g_rowptr[v + 1];
        end = min(end, e); beg = max(min(beg, end), 0);   // defensive clamp
        // --- per-receiver edge-feature sums (cf, cnt) ---
        float4 cf;
        float cn;
        if (FIRST) {
            cf = make_float4(0.f, 0.f, 0.f, 0.f);
            cn = 0.f;
            for (int j = beg + lane; j < end; j += 32) {
                uint4 r = g_rec[j];
                float2 e01 = __half22float2(*(const __half2*)&r.z);
                float2 e23 = __half22float2(*(const __half2*)&r.w);
                cf.x += e01.x; cf.y += e01.y; cf.z += e23.x; cf.w += e23.y;
                cn += __uint_as_float(r.y);
            }
#pragma unroll
            for (int off = 16; off > 0; off >>= 1) {
                cf.x += __shfl_xor_sync(WARP_FULL, cf.x, off);
                cf.y += __shfl_xor_sync(WARP_FULL, cf.y, off);
                cf.z += __shfl_xor_sync(WARP_FULL, cf.z, off);
                cf.w += __shfl_xor_sync(WARP_FULL, cf.w, off);
                cn   += __shfl_xor_sync(WARP_FULL, cn, off);
            }
            if (lane == 0) {
                *(float4*)&g_Cfeat[(size_t)v * 4] = cf;
                g_Ccnt[v] = cn;
            }
        } else {
            cf = *(const float4*)&g_Cfeat[(size_t)v * 4];
            cn = g_Ccnt[v];
        }
        // --- main edge loop: 8 edges/iter, 4 lanes/edge, DEPTH-3 gather pipeline ---
        float acc[8];
#pragma unroll
        for (int i = 0; i < 8; i++) acc[i] = 0.f;
        int j0 = beg + sub;
        uint4 r0 = make_uint4(0u, 0u, 0u, 0u);
        uint4 r1 = make_uint4(0u, 0u, 0u, 0u);
        uint4 r2 = make_uint4(0u, 0u, 0u, 0u);
        if (j0 < end) r0 = g_rec[j0];
        uint4 a0 = *(const uint4*)(g_Ah + (size_t)min(r0.x, nm1) * HD + (q << 3));
        if (j0 + 8 < end) r1 = g_rec[j0 + 8];
        uint4 a1 = *(const uint4*)(g_Ah + (size_t)min(r1.x, nm1) * HD + (q << 3));
        if (j0 + 16 < end) r2 = g_rec[j0 + 16];
        uint4 a2 = *(const uint4*)(g_Ah + (size_t)min(r2.x, nm1) * HD + (q << 3));
        for (int base = beg; base < end; base += 8) {
            float cmk = __uint_as_float(r0.y);
            uint4 a = a0;
            r0 = r1; a0 = a1;
            r1 = r2; a1 = a2;
            int nj = base + 24 + sub;
            r2 = make_uint4(0u, 0u, 0u, 0u);
            if (nj < end) r2 = g_rec[nj];
            a2 = *(const uint4*)(g_Ah + (size_t)min(r2.x, nm1) * HD + (q << 3));
            float2 f0 = __half22float2(*(const __half2*)&a.x);
            float2 f1 = __half22float2(*(const __half2*)&a.y);
            float2 f2 = __half22float2(*(const __half2*)&a.z);
            float2 f3 = __half22float2(*(const __half2*)&a.w);
            acc[0] += cmk * f0.x; acc[1] += cmk * f0.y;
            acc[2] += cmk * f1.x; acc[3] += cmk * f1.y;
            acc[4] += cmk * f2.x; acc[5] += cmk * f2.y;
            acc[6] += cmk * f3.x; acc[7] += cmk * f3.y;
        }
#pragma unroll
        for (int off = 4; off < 32; off <<= 1) {
#pragma unroll
            for (int i = 0; i < 8; i++)
                acc[i] += __shfl_xor_sync(WARP_FULL, acc[i], off);
        }
        if (sub == 0) {   // lanes 0..3: lane q owns cols q*8..q*8+7
            int c0 = q << 3;
            float hv[8];
#pragma unroll
            for (int i = 0; i < 8; i++) {
                int c = c0 + i;
                float t = acc[i] + cf.x * sW2[0][c] + cf.y * sW2[1][c] +
                          cf.z * sW2[2][c] + cf.w * sW2[3][c] + cn * sb[c];
                hv[i] = fmaxf(t, 0.f);
                pacc[i] += hv[i];
            }
            float* hrow = g_h + (size_t)v * HD + c0;
            *(float4*)(hrow + 0) = make_float4(hv[0], hv[1], hv[2], hv[3]);
            *(float4*)(hrow + 4) = make_float4(hv[4], hv[5], hv[6], hv[7]);
        }
    }
    if ((lane >> 2) == 0) {
        int c0 = q << 3;
#pragma unroll
        for (int i = 0; i < 8; i++) atomicAdd(&spool[c0 + i], pacc[i]);
    }
    __syncthreads();
    if (tid < HD) atomicAdd(&g_pooled[layer * HD + tid], spool[tid]);
}

// ---------------------------------------------------------------- node update: thread-per-node, smem-staged
template <bool LAST>
__global__ __launch_bounds__(256) void k_upd(
    const float* __restrict__ Wg, const float* __restrict__ bg,
    const float* __restrict__ Wn, const float* __restrict__ bn,
    const float* __restrict__ Wo, const float* __restrict__ bo,
    const float* __restrict__ WmNext,
    float* __restrict__ out, int layer, float invn, int n) {
    __shared__ float sWn[HD * HD], sWm[34 * HD], sWo0[HD], sWo1[HD], gterm[HD], sgnew[HD];
    __shared__ float sh[TILE][HD + 1];
    int tid = threadIdx.x;
    for (int i = tid; i < HD * HD; i += 256) sWn[i] = Wn[i];   // rows 0..31 (h part)
    if (!LAST)
        for (int i = tid; i < 34 * HD; i += 256) sWm[i] = WmNext[i];
    if (tid < HD) {
        sWo0[tid] = Wo[tid * 2 + 0];
        sWo1[tid] = Wo[tid * 2 + 1];
        // inline supernode update (reads only pre-kernel state)
        float acc = bg[tid];
#pragma unroll
        for (int k = 0; k < HD; k++) acc += g_gst2[layer][k] * Wg[k * HD + tid];
#pragma unroll
        for (int k = 0; k < HD; k++)
            acc += (g_pooled[layer * HD + k] * invn) * Wg[(HD + k) * HD + tid];
        float gn = fmaxf(acc, 0.f);
        sgnew[tid] = gn;
        if (blockIdx.x == 0) g_gst2[layer + 1][tid] = gn;
    }
    __syncthreads();
    if (tid < HD) {
        float gt = bn[tid];
#pragma unroll
        for (int k = 0; k < HD; k++) gt += sgnew[k] * Wn[(HD + k) * HD + tid];
        gterm[tid] = gt;
    }
    float bo0 = bo[0], bo1 = bo[1];
    for (int tb = blockIdx.x * TILE; tb < n; tb += gridDim.x * TILE) {
        int nt = min(TILE, n - tb);
        __syncthreads();   // also orders gterm/sgnew writes before reads below
        for (int i = tid; i < nt * HD; i += 256)
            sh[i >> 5][i & 31] = g_h[(size_t)tb * HD + i];
        __syncthreads();
        int node = tb + tid;
        if (tid < nt) {
            float acc[HD];
#pragma unroll
            for (int c = 0; c < HD; c++) acc[c] = gterm[c];
#pragma unroll
            for (int k = 0; k < HD; k++) {
                float hk = sh[tid][k];
#pragma unroll
                for (int c = 0; c < HD; c++) acc[c] += hk * sWn[k * HD + c];
            }
            float p0 = 0.f, p1 = 0.f;
#pragma unroll
            for (int c = 0; c < HD; c++) {
                acc[c] = fmaxf(acc[c], 0.f);
                p0 += acc[c] * sWo0[c];
                p1 += acc[c] * sWo1[c];
            }
            float2 Vold = *(const float2*)&g_V[(size_t)node * 2];
            float V0 = Vold.x + p0 + bo0;
            float V1 = Vold.y + p1 + bo1;
            if (LAST) {
                *(float2*)&out[(size_t)node * 2] = make_float2(V0, V1);
            } else {
                *(float2*)&g_V[(size_t)node * 2] = make_float2(V0, V1);
                float a2[HD];
#pragma unroll
                for (int c = 0; c < HD; c++) a2[c] = V0 * sWm[c] + V1 * sWm[HD + c];
#pragma unroll
                for (int k = 0; k < HD; k++) {
                    float hk = acc[k];
#pragma unroll
                    for (int c = 0; c < HD; c++) a2[c] += hk * sWm[(2 + k) * HD + c];
                }
                size_t base = (size_t)node * HD;
#pragma unroll
                for (int i = 0; i < 4; i++) {
                    __half2 h0 = __floats2half2_rn(a2[i * 8 + 0], a2[i * 8 + 1]);
                    __half2 h1 = __floats2half2_rn(a2[i * 8 + 2], a2[i * 8 + 3]);
                    __half2 h2 = __floats2half2_rn(a2[i * 8 + 4], a2[i * 8 + 5]);
                    __half2 h3 = __floats2half2_rn(a2[i * 8 + 6], a2[i * 8 + 7]);
                    uint4 w;
                    w.x = *(unsigned*)&h0; w.y = *(unsigned*)&h1;
                    w.z = *(unsigned*)&h2; w.w = *(unsigned*)&h3;
                    *(uint4*)(g_Ah + base + i * 8) = w;
                }
            }
        }
    }
}

// ---------------------------------------------------------------- launcher
extern "C" void kernel_launch(void* const* d_in, const int* in_sizes, int n_in,
                              void* d_out, int out_size) {
    const float* PQ    = (const float*)d_in[0];
    const int*   send  = (const int*)d_in[1];
    const int*   recv  = (const int*)d_in[2];
    const float* ef    = (const float*)d_in[3];
    const float* emask = (const float*)d_in[4];
    const float* Win   = (const float*)d_in[5];
    const float* bin   = (const float*)d_in[6];
    const float* Wmsg  = (const float*)d_in[7];
    const float* bmsg  = (const float*)d_in[8];
    const float* Wg    = (const float*)d_in[9];
    const float* bg    = (const float*)d_in[10];
    const float* Wn    = (const float*)d_in[11];
    const float* bn    = (const float*)d_in[12];
    const float* Wo    = (const float*)d_in[13];
    const float* bo    = (const float*)d_in[14];
    float* out = (float*)d_out;

    int n = in_sizes[0] / 2;
    int e = in_sizes[1];

    const int PB = 1184;
    const int EB = 2048;
    int nch = (n + SCAN_CHUNK - 1) / SCAN_CHUNK;
    int upb = (n + TILE - 1) / TILE;

    // launch 0..2: CSR build + init (+ state reset inside k_scatter)
    k_histinit<<<PB, 256>>>(recv, e, (const float2*)PQ, Win, bin, Wmsg, n);
    k_scan<<<nch, 1024>>>(n, e);
    k_scatter<<<EB, 256>>>(send, recv, emask, (const float4*)ef, e, n);

    float invn = 1.f / (float)n;
    for (int l = 0; l < NLAYER; l++) {
        // launch 3 (layer 0) is the ncu-profiled launch
        if (l == 0)
            k_agg<true><<<PB, 256>>>(Wmsg + (size_t)(l * 38 + 34) * HD, bmsg + l * HD, l, n, e);
        else
            k_agg<false><<<PB, 256>>>(Wmsg + (size_t)(l * 38 + 34) * HD, bmsg + l * HD, l, n, e);
        if (l < NLAYER - 1)
            k_upd<false><<<upb, 256>>>(Wg + (size_t)l * 64 * HD, bg + l * HD,
                                       Wn + (size_t)l * 64 * HD, bn + l * HD,
                                       Wo + (size_t)l * HD * 2, bo + l * 2,
                                       Wmsg + (size_t)(l + 1) * 38 * HD, out, l, invn, n);
        else
            k_upd<true><<<upb, 256>>>(Wg + (size_t)l * 64 * HD, bg + l * HD,
                                      Wn + (size_t)l * 64 * HD, bn + l * HD,
                                      Wo + (size_t)l * HD * 2, bo + l * 2,
                                      nullptr, out, l, invn, n);
    }
}

// round 17
// speedup vs baseline: 1.3410x; 1.1781x over previous
#include <cuda_runtime.h>
#include <cuda_fp16.h>

#define WARP_FULL 0xFFFFFFFFu

namespace {
constexpr int NMAX = 100000;
constexpr int EMAX = 3200000;
constexpr int HD = 32;
constexpr int NLAYER = 3;
constexpr int SCAN_CHUNK = 4096;   // 1024 threads * 4 items
constexpr int MAXCHUNK = 64;
constexpr int TILE = 256;          // nodes per block-tile in thread-per-node kernels
}

// ---- persistent device scratch (module-load zero-init; no runtime allocs) ----
__device__ __align__(128) __half g_Ah[(size_t)NMAX * HD];   // fp16 message precursor rows (64 B/row)
__device__ __align__(128) float  g_h[(size_t)NMAX * HD];
__device__ __align__(16)  float  g_V[(size_t)NMAX * 2];
__device__ __align__(16)  float  g_Cfeat[(size_t)NMAX * 4];
__device__ float g_Ccnt[NMAX];
__device__ int   g_deg[NMAX];        // zero at entry (reset by k_scatter of previous call)
__device__ int   g_rowptr[NMAX + 1];
__device__ int   g_cursor[NMAX];
// one 16-byte record per edge, CSR order: {send, mask bits, half2(mask*ef01), half2(mask*ef23)}
__device__ __align__(128) uint4 g_rec[EMAX];
__device__ float g_pooled[NLAYER * HD];           // zero at entry (reset by k_scatter)
__device__ float g_gst2[NLAYER + 1][HD];          // gst2[0] zero at entry (reset by k_scatter)
__device__ int   g_scanstate[MAXCHUNK];           // zero at entry (reset by k_scatter)

// ---------------------------------------------------------------- launch 0: histogram + A0/V init (thread-per-node)
__global__ __launch_bounds__(256) void k_histinit(
    const int* __restrict__ recv, int e,
    const float2* __restrict__ PQ, const float* __restrict__ Win,
    const float* __restrict__ bin, const float* __restrict__ Wmsg0, int n) {
    __shared__ float sWin0[HD], sWin1[HD], sbin[HD], sWm[34 * HD];
    int tid = threadIdx.x;
    if (tid < HD) { sWin0[tid] = Win[tid]; sWin1[tid] = Win[HD + tid]; sbin[tid] = bin[tid]; }
    for (int i = tid; i < 34 * HD; i += 256) sWm[i] = Wmsg0[i];
    __syncthreads();

    // phase 1: receiver histogram (index clamped)
    int gid = blockIdx.x * 256 + tid, gs = gridDim.x * 256;
    for (int i = gid; i < e; i += gs) {
        int r = recv[i];
        r = min(max(r, 0), n - 1);
        atomicAdd(&g_deg[r], 1);
    }

    // phase 2: thread-per-node A0 = [1,0,h0] @ Wmsg0[:34]; V init
    for (int tb = blockIdx.x * TILE; tb < n; tb += gridDim.x * TILE) {
        int node = tb + tid;
        if (node < n) {
            float2 pq = PQ[node];
            float h0[HD];
#pragma unroll
            for (int c = 0; c < HD; c++)
                h0[c] = pq.x * sWin0[c] + pq.y * sWin1[c] + sbin[c];
            float a[HD];
#pragma unroll
            for (int c = 0; c < HD; c++) a[c] = sWm[c];   // V = (1,0): row 0
#pragma unroll
            for (int k = 0; k < HD; k++) {
                float hk = h0[k];
#pragma unroll
                for (int c = 0; c < HD; c++) a[c] += hk * sWm[(2 + k) * HD + c];
            }
            size_t base = (size_t)node * HD;
#pragma unroll
            for (int i = 0; i < 4; i++) {
                __half2 p0 = __floats2half2_rn(a[i * 8 + 0], a[i * 8 + 1]);
                __half2 p1 = __floats2half2_rn(a[i * 8 + 2], a[i * 8 + 3]);
                __half2 p2 = __floats2half2_rn(a[i * 8 + 4], a[i * 8 + 5]);
                __half2 p3 = __floats2half2_rn(a[i * 8 + 6], a[i * 8 + 7]);
                uint4 w;
                w.x = *(unsigned*)&p0; w.y = *(unsigned*)&p1;
                w.z = *(unsigned*)&p2; w.w = *(unsigned*)&p3;
                *(uint4*)(g_Ah + base + i * 8) = w;
            }
            *(float2*)&g_V[(size_t)node * 2] = make_float2(1.f, 0.f);
        }
    }
}

// ---------------------------------------------------------------- launch 1: single-kernel scan (decoupled lookback)
__global__ void k_scan(int n, int e) {
    int b = blockIdx.x, t = threadIdx.x;
    int base = b * SCAN_CHUNK + t * 4;
    int d0 = 0, d1 = 0, d2 = 0, d3 = 0;
    if (base + 0 < n) d0 = g_deg[base + 0];
    if (base + 1 < n) d1 = g_deg[base + 1];
    if (base + 2 < n) d2 = g_deg[base + 2];
    if (base + 3 < n) d3 = g_deg[base + 3];
    int tsum = d0 + d1 + d2 + d3;
    __shared__ int sc[1024];
    sc[t] = tsum; __syncthreads();
    for (int off = 1; off < 1024; off <<= 1) {
        int v = (t >= off) ? sc[t - off] : 0;
        __syncthreads();
        sc[t] += v;
        __syncthreads();
    }
    __shared__ int s_off;
    if (t == 0) {
        int agg = sc[1023];
        int off = 0;
        if (b == 0) {
            atomicExch(&g_scanstate[0], (agg << 2) | 2);
            g_rowptr[n] = e;
        } else {
            atomicExch(&g_scanstate[b], (agg << 2) | 1);
            int p = b - 1;
            while (p >= 0) {
                int s;
                do { s = atomicAdd(&g_scanstate[p], 0); } while ((s & 3) == 0);
                off += (s >> 2);
                if ((s & 3) == 2) break;
                p--;
            }
            atomicExch(&g_scanstate[b], ((off + agg) << 2) | 2);
        }
        s_off = off;
    }
    __syncthreads();
    int excl = sc[t] - tsum + s_off;
    int p0 = excl, p1 = excl + d0, p2 = p1 + d1, p3 = p2 + d2;
    if (base + 0 < n) { g_rowptr[base + 0] = p0; g_cursor[base + 0] = p0; }
    if (base + 1 < n) { g_rowptr[base + 1] = p1; g_cursor[base + 1] = p1; }
    if (base + 2 < n) { g_rowptr[base + 2] = p2; g_cursor[base + 2] = p2; }
    if (base + 3 < n) { g_rowptr[base + 3] = p3; g_cursor[base + 3] = p3; }
}

// ---------------------------------------------------------------- launch 2: scatter 16B edge records + state reset
__global__ __launch_bounds__(256) void k_scatter(
    const int* __restrict__ send, const int* __restrict__ recv,
    const float* __restrict__ mask, const float4* __restrict__ ef, int e, int n) {
    int gid = blockIdx.x * blockDim.x + threadIdx.x;
    int stride = gridDim.x * blockDim.x;
    for (int i = gid; i < e; i += stride) {
        int r = recv[i];
        r = min(max(r, 0), n - 1);
        int pos = atomicAdd(&g_cursor[r], 1);
        pos = min(max(pos, 0), EMAX - 1);      // defensive clamp (inert if CSR intact)
        float mk = mask[i];
        float4 f = ef[i];
        __half2 e01 = __floats2half2_rn(mk * f.x, mk * f.y);
        __half2 e23 = __floats2half2_rn(mk * f.z, mk * f.w);
        uint4 rec;
        rec.x = (unsigned)min(max(send[i], 0), n - 1);
        rec.y = __float_as_uint(mk);
        rec.z = *(unsigned*)&e01;
        rec.w = *(unsigned*)&e23;
        g_rec[pos] = rec;
    }
    // state reset for next call/replay: g_deg & g_scanstate already consumed
    // (launch 1); g_pooled & g_gst2[0] have no consumer until launch 3+.
    for (int i = gid; i < n; i += stride) g_deg[i] = 0;
    if (gid < MAXCHUNK) g_scanstate[gid] = 0;
    if (gid < NLAYER * HD) g_pooled[gid] = 0.f;
    if (gid < HD) g_gst2[0][gid] = 0.f;
}

// ---------------------------------------------------------------- launch 3 (PROFILED): hot SpMM h = relu(S @ A + D)
// TWO rows per warp: 16 lanes per row (4 edge slots x 4 column quarters).
// Amortizes per-row prologue/epilogue; reduction = xor 4,8 within each half.
template <bool FIRST>
__global__ __launch_bounds__(256) void k_agg(
    const float* __restrict__ W2,   // W_msg[l] rows 34..37 (4x32)
    const float* __restrict__ bm,   // b_msg[l]
    int layer, int n, int e) {
    __shared__ float sW2[4][HD], sb[HD], spool[HD];
    int tid = threadIdx.x;
    if (tid < 4 * HD) sW2[tid >> 5][tid & 31] = W2[tid];
    if (tid < HD) { sb[tid] = bm[tid]; spool[tid] = 0.f; }
    __syncthreads();
    const unsigned nm1 = (unsigned)(n - 1);
    int lane = tid & 31;
    int half = lane >> 4;          // row within pair (0 or 1)
    int hl   = lane & 15;          // lane within half
    int sub  = hl >> 2;            // edge slot 0..3
    int q    = lane & 3;           // column quarter: cols q*8 .. q*8+7
    int wpb = blockDim.x >> 5;
    int gw = blockIdx.x * wpb + (tid >> 5), nw = gridDim.x * wpb;
    int npairs = (n + 1) >> 1;
    float pacc[8];
#pragma unroll
    for (int i = 0; i < 8; i++) pacc[i] = 0.f;
    for (int vp = gw; vp < npairs; vp += nw) {
        int v = vp * 2 + half;
        bool valid = v < n;
        int beg = 0, end = 0;
        if (valid) {
            beg = g_rowptr[v];
            end = g_rowptr[v + 1];
            end = min(end, e); beg = max(min(beg, end), 0);   // defensive clamp
        }
        // --- per-receiver edge-feature sums (cf, cnt) ---
        float4 cf;
        float cn;
        if (FIRST) {
            cf = make_float4(0.f, 0.f, 0.f, 0.f);
            cn = 0.f;
            for (int j = beg + hl; j < end; j += 16) {
                uint4 r = g_rec[j];
                float2 e01 = __half22float2(*(const __half2*)&r.z);
                float2 e23 = __half22float2(*(const __half2*)&r.w);
                cf.x += e01.x; cf.y += e01.y; cf.z += e23.x; cf.w += e23.y;
                cn += __uint_as_float(r.y);
            }
#pragma unroll
            for (int off = 1; off < 16; off <<= 1) {
                cf.x += __shfl_xor_sync(WARP_FULL, cf.x, off);
                cf.y += __shfl_xor_sync(WARP_FULL, cf.y, off);
                cf.z += __shfl_xor_sync(WARP_FULL, cf.z, off);
                cf.w += __shfl_xor_sync(WARP_FULL, cf.w, off);
                cn   += __shfl_xor_sync(WARP_FULL, cn, off);
            }
            if (hl == 0 && valid) {
                *(float4*)&g_Cfeat[(size_t)v * 4] = cf;
                g_Ccnt[v] = cn;
            }
        } else {
            cf = make_float4(0.f, 0.f, 0.f, 0.f);
            cn = 0.f;
            if (valid) {
                cf = *(const float4*)&g_Cfeat[(size_t)v * 4];
                cn = g_Ccnt[v];
            }
        }
        // --- main edge loop: 4 edges/iter per row, 4 lanes/edge, depth-2 pipeline ---
        float acc[8];
#pragma unroll
        for (int i = 0; i < 8; i++) acc[i] = 0.f;
        int j0 = beg + sub;
        uint4 r0 = make_uint4(0u, 0u, 0u, 0u), r1 = make_uint4(0u, 0u, 0u, 0u);
        if (j0 < end) r0 = g_rec[j0];
        uint4 a0 = *(const uint4*)(g_Ah + (size_t)min(r0.x, nm1) * HD + (q << 3));
        if (j0 + 4 < end) r1 = g_rec[j0 + 4];
        uint4 a1 = *(const uint4*)(g_Ah + (size_t)min(r1.x, nm1) * HD + (q << 3));
        for (int base = beg; base < end; base += 4) {
            float cmk = __uint_as_float(r0.y);
            uint4 a = a0;
            r0 = r1; a0 = a1;
            int nj = base + 8 + sub;
            r1 = make_uint4(0u, 0u, 0u, 0u);
            if (nj < end) r1 = g_rec[nj];
            a1 = *(const uint4*)(g_Ah + (size_t)min(r1.x, nm1) * HD + (q << 3));
            float2 f0 = __half22float2(*(const __half2*)&a.x);
            float2 f1 = __half22float2(*(const __half2*)&a.y);
            float2 f2 = __half22float2(*(const __half2*)&a.z);
            float2 f3 = __half22float2(*(const __half2*)&a.w);
            acc[0] += cmk * f0.x; acc[1] += cmk * f0.y;
            acc[2] += cmk * f1.x; acc[3] += cmk * f1.y;
            acc[4] += cmk * f2.x; acc[5] += cmk * f2.y;
            acc[6] += cmk * f3.x; acc[7] += cmk * f3.y;
        }
        // reduce across the 4 edge slots within each half (strides 4, 8)
#pragma unroll
        for (int off = 4; off < 16; off <<= 1) {
#pragma unroll
            for (int i = 0; i < 8; i++)
                acc[i] += __shfl_xor_sync(WARP_FULL, acc[i], off);
        }
        if (sub == 0 && valid) {   // lanes 0..3 (half 0) / 16..19 (half 1)
            int c0 = q << 3;
            float hv[8];
#pragma unroll
            for (int i = 0; i < 8; i++) {
                int c = c0 + i;
                float t = acc[i] + cf.x * sW2[0][c] + cf.y * sW2[1][c] +
                          cf.z * sW2[2][c] + cf.w * sW2[3][c] + cn * sb[c];
                hv[i] = fmaxf(t, 0.f);
                pacc[i] += hv[i];
            }
            float* hrow = g_h + (size_t)v * HD + c0;
            *(float4*)(hrow + 0) = make_float4(hv[0], hv[1], hv[2], hv[3]);
            *(float4*)(hrow + 4) = make_float4(hv[4], hv[5], hv[6], hv[7]);
        }
    }
    // combine pool partials across the two halves, then one atomic set per warp
#pragma unroll
    for (int i = 0; i < 8; i++)
        pacc[i] += __shfl_xor_sync(WARP_FULL, pacc[i], 16);
    if (lane < 4) {
        int c0 = q << 3;
#pragma unroll
        for (int i = 0; i < 8; i++) atomicAdd(&spool[c0 + i], pacc[i]);
    }
    __syncthreads();
    if (tid < HD) atomicAdd(&g_pooled[layer * HD + tid], spool[tid]);
}

// ---------------------------------------------------------------- node update: thread-per-node, smem-staged
template <bool LAST>
__global__ __launch_bounds__(256) void k_upd(
    const float* __restrict__ Wg, const float* __restrict__ bg,
    const float* __restrict__ Wn, const float* __restrict__ bn,
    const float* __restrict__ Wo, const float* __restrict__ bo,
    const float* __restrict__ WmNext,
    float* __restrict__ out, int layer, float invn, int n) {
    __shared__ float sWn[HD * HD], sWm[34 * HD], sWo0[HD], sWo1[HD], gterm[HD], sgnew[HD];
    __shared__ float sh[TILE][HD + 1];
    int tid = threadIdx.x;
    for (int i = tid; i < HD * HD; i += 256) sWn[i] = Wn[i];   // rows 0..31 (h part)
    if (!LAST)
        for (int i = tid; i < 34 * HD; i += 256) sWm[i] = WmNext[i];
    if (tid < HD) {
        sWo0[tid] = Wo[tid * 2 + 0];
        sWo1[tid] = Wo[tid * 2 + 1];
        // inline supernode update (reads only pre-kernel state)
        float acc = bg[tid];
#pragma unroll
        for (int k = 0; k < HD; k++) acc += g_gst2[layer][k] * Wg[k * HD + tid];
#pragma unroll
        for (int k = 0; k < HD; k++)
            acc += (g_pooled[layer * HD + k] * invn) * Wg[(HD + k) * HD + tid];
        float gn = fmaxf(acc, 0.f);
        sgnew[tid] = gn;
        if (blockIdx.x == 0) g_gst2[layer + 1][tid] = gn;
    }
    __syncthreads();
    if (tid < HD) {
        float gt = bn[tid];
#pragma unroll
        for (int k = 0; k < HD; k++) gt += sgnew[k] * Wn[(HD + k) * HD + tid];
        gterm[tid] = gt;
    }
    float bo0 = bo[0], bo1 = bo[1];
    for (int tb = blockIdx.x * TILE; tb < n; tb += gridDim.x * TILE) {
        int nt = min(TILE, n - tb);
        __syncthreads();   // also orders gterm/sgnew writes before reads below
        for (int i = tid; i < nt * HD; i += 256)
            sh[i >> 5][i & 31] = g_h[(size_t)tb * HD + i];
        __syncthreads();
        int node = tb + tid;
        if (tid < nt) {
            float acc[HD];
#pragma unroll
            for (int c = 0; c < HD; c++) acc[c] = gterm[c];
#pragma unroll
            for (int k = 0; k < HD; k++) {
                float hk = sh[tid][k];
#pragma unroll
                for (int c = 0; c < HD; c++) acc[c] += hk * sWn[k * HD + c];
            }
            float p0 = 0.f, p1 = 0.f;
#pragma unroll
            for (int c = 0; c < HD; c++) {
                acc[c] = fmaxf(acc[c], 0.f);
                p0 += acc[c] * sWo0[c];
                p1 += acc[c] * sWo1[c];
            }
            float2 Vold = *(const float2*)&g_V[(size_t)node * 2];
            float V0 = Vold.x + p0 + bo0;
            float V1 = Vold.y + p1 + bo1;
            if (LAST) {
                *(float2*)&out[(size_t)node * 2] = make_float2(V0, V1);
            } else {
                *(float2*)&g_V[(size_t)node * 2] = make_float2(V0, V1);
                float a2[HD];
#pragma unroll
                for (int c = 0; c < HD; c++) a2[c] = V0 * sWm[c] + V1 * sWm[HD + c];
#pragma unroll
                for (int k = 0; k < HD; k++) {
                    float hk = acc[k];
#pragma unroll
                    for (int c = 0; c < HD; c++) a2[c] += hk * sWm[(2 + k) * HD + c];
                }
                size_t base = (size_t)node * HD;
#pragma unroll
                for (int i = 0; i < 4; i++) {
                    __half2 h0 = __floats2half2_rn(a2[i * 8 + 0], a2[i * 8 + 1]);
                    __half2 h1 = __floats2half2_rn(a2[i * 8 + 2], a2[i * 8 + 3]);
                    __half2 h2 = __floats2half2_rn(a2[i * 8 + 4], a2[i * 8 + 5]);
                    __half2 h3 = __floats2half2_rn(a2[i * 8 + 6], a2[i * 8 + 7]);
                    uint4 w;
                    w.x = *(unsigned*)&h0; w.y = *(unsigned*)&h1;
                    w.z = *(unsigned*)&h2; w.w = *(unsigned*)&h3;
                    *(uint4*)(g_Ah + base + i * 8) = w;
                }
            }
        }
    }
}

// ---------------------------------------------------------------- launcher
extern "C" void kernel_launch(void* const* d_in, const int* in_sizes, int n_in,
                              void* d_out, int out_size) {
    const float* PQ    = (const float*)d_in[0];
    const int*   send  = (const int*)d_in[1];
    const int*   recv  = (const int*)d_in[2];
    const float* ef    = (const float*)d_in[3];
    const float* emask = (const float*)d_in[4];
    const float* Win   = (const float*)d_in[5];
    const float* bin   = (const float*)d_in[6];
    const float* Wmsg  = (const float*)d_in[7];
    const float* bmsg  = (const float*)d_in[8];
    const float* Wg    = (const float*)d_in[9];
    const float* bg    = (const float*)d_in[10];
    const float* Wn    = (const float*)d_in[11];
    const float* bn    = (const float*)d_in[12];
    const float* Wo    = (const float*)d_in[13];
    const float* bo    = (const float*)d_in[14];
    float* out = (float*)d_out;

    int n = in_sizes[0] / 2;
    int e = in_sizes[1];

    const int PB = 1184;
    const int EB = 2048;
    int nch = (n + SCAN_CHUNK - 1) / SCAN_CHUNK;
    int upb = (n + TILE - 1) / TILE;

    // launch 0..2: CSR build + init (+ state reset inside k_scatter)
    k_histinit<<<PB, 256>>>(recv, e, (const float2*)PQ, Win, bin, Wmsg, n);
    k_scan<<<nch, 1024>>>(n, e);
    k_scatter<<<EB, 256>>>(send, recv, emask, (const float4*)ef, e, n);

    float invn = 1.f / (float)n;
    for (int l = 0; l < NLAYER; l++) {
        // launch 3 (layer 0) is the ncu-profiled launch
        if (l == 0)
            k_agg<true><<<PB, 256>>>(Wmsg + (size_t)(l * 38 + 34) * HD, bmsg + l * HD, l, n, e);
        else
            k_agg<false><<<PB, 256>>>(Wmsg + (size_t)(l * 38 + 34) * HD, bmsg + l * HD, l, n, e);
        if (l < NLAYER - 1)
            k_upd<false><<<upb, 256>>>(Wg + (size_t)l * 64 * HD, bg + l * HD,
                                       Wn + (size_t)l * 64 * HD, bn + l * HD,
                                       Wo + (size_t)l * HD * 2, bo + l * 2,
                                       Wmsg + (size_t)(l + 1) * 38 * HD, out, l, invn, n);
        else
            k_upd<true><<<upb, 256>>>(Wg + (size_t)l * 64 * HD, bg + l * HD,
                                      Wn + (size_t)l * 64 * HD, bn + l * HD,
                                      Wo + (size_t)l * HD * 2, bo + l * 2,
                                      nullptr, out, l, invn, n);
    }
}